// round 3
// baseline (speedup 1.0000x reference)
#include <cuda_runtime.h>

#define OMEGA 1.7f

// -------- global scratch (allocations are forbidden) --------
__device__ float g_Mop[64 * 256];
__device__ float g_h1[4096 * 512];
__device__ float g_h2[4096 * 512];
__device__ float g_y0[4096 * 256];

// =====================================================================
// setup: G = A A^T (64x64), K = inv(G) via Gauss-Jordan, Mop = K @ A
// one CTA, 256 threads
// =====================================================================
#define SETUP_SMEM ((64 * 260 + 64 * 130) * 4)

__global__ void setup_kernel(const float* __restrict__ A) {
    extern __shared__ float sm[];
    float* As = sm;              // [64][260] staged A
    float* G  = sm + 64 * 260;   // [64][130] augmented [G | I]
    __shared__ float colp[64];
    const int tid = threadIdx.x;

    for (int i = tid; i < 64 * 64; i += 256) {
        int m = i >> 6, d = (i & 63) << 2;
        *(float4*)(As + m * 260 + d) = *(const float4*)(A + m * 256 + d);
    }
    __syncthreads();

    for (int o = tid; o < 64 * 64; o += 256) {
        int i = o >> 6, j = o & 63;
        const float4* ai = (const float4*)(As + i * 260);
        const float4* aj = (const float4*)(As + j * 260);
        float s = 0.f;
        #pragma unroll 8
        for (int d4 = 0; d4 < 64; d4++) {
            float4 a = ai[d4], b = aj[d4];
            s += a.x * b.x + a.y * b.y + a.z * b.z + a.w * b.w;
        }
        G[i * 130 + j] = s;
        G[i * 130 + 64 + j] = (i == j) ? 1.f : 0.f;
    }
    __syncthreads();

    for (int p = 0; p < 64; p++) {
        float pinv = 1.f / G[p * 130 + p];
        if (tid < 64) colp[tid] = G[tid * 130 + p];
        __syncthreads();
        if (tid < 128) G[p * 130 + tid] *= pinv;
        __syncthreads();
        for (int e = tid; e < 64 * 128; e += 256) {
            int i = e >> 7, c = e & 127;
            if (i != p) G[i * 130 + c] -= colp[i] * G[p * 130 + c];
        }
        __syncthreads();
    }

    for (int o = tid; o < 64 * 256; o += 256) {
        int m = o >> 8, d = o & 255;
        float s = 0.f;
        #pragma unroll 8
        for (int j = 0; j < 64; j++) s += G[m * 130 + 64 + j] * As[j * 260 + d];
        g_Mop[o] = s;
    }
}

// =====================================================================
// trunk GEMM: C = act(Amat @ Bmat + bias), BM=128 BN=64 BK=16, 256 thr
// =====================================================================
template <bool RELU>
__global__ void gemm_bias(const float* __restrict__ Am, const float* __restrict__ Bm,
                          const float* __restrict__ bias, float* __restrict__ C,
                          int M, int N, int K) {
    __shared__ float As[16][132];
    __shared__ float Bs[16][68];
    const int tid = threadIdx.x;
    const int bm = blockIdx.y * 128, bn = blockIdx.x * 64;
    const int tx = tid & 15, ty = tid >> 4;

    float acc[8][4];
    #pragma unroll
    for (int i = 0; i < 8; i++)
        #pragma unroll
        for (int j = 0; j < 4; j++) acc[i][j] = 0.f;

    const int ar = tid >> 2, akc = (tid & 3) << 2;
    const int bkr = tid >> 4, bnc = (tid & 15) << 2;

    for (int k0 = 0; k0 < K; k0 += 16) {
        #pragma unroll
        for (int rr = 0; rr < 2; rr++) {
            int r = ar + rr * 64;
            float4 v = *(const float4*)(Am + (size_t)(bm + r) * K + k0 + akc);
            As[akc + 0][r] = v.x; As[akc + 1][r] = v.y;
            As[akc + 2][r] = v.z; As[akc + 3][r] = v.w;
        }
        *(float4*)(&Bs[bkr][bnc]) = *(const float4*)(Bm + (size_t)(k0 + bkr) * N + bn + bnc);
        __syncthreads();

        #pragma unroll
        for (int kk = 0; kk < 16; kk++) {
            float a[8], b[4];
            #pragma unroll
            for (int i = 0; i < 8; i++) a[i] = As[kk][ty * 8 + i];
            #pragma unroll
            for (int j = 0; j < 4; j++) b[j] = Bs[kk][tx * 4 + j];
            #pragma unroll
            for (int i = 0; i < 8; i++)
                #pragma unroll
                for (int j = 0; j < 4; j++) acc[i][j] = fmaf(a[i], b[j], acc[i][j]);
        }
        __syncthreads();
    }

    float4 bv = *(const float4*)(bias + bn + tx * 4);
    #pragma unroll
    for (int i = 0; i < 8; i++) {
        float4 o;
        o.x = acc[i][0] + bv.x; o.y = acc[i][1] + bv.y;
        o.z = acc[i][2] + bv.z; o.w = acc[i][3] + bv.w;
        if (RELU) {
            o.x = fmaxf(o.x, 0.f); o.y = fmaxf(o.y, 0.f);
            o.z = fmaxf(o.z, 0.f); o.w = fmaxf(o.w, 0.f);
        }
        *(float4*)(C + (size_t)(bm + ty * 8 + i) * N + bn + tx * 4) = o;
    }
}

// =====================================================================
// iteration kernel: persistent 32-row tile, all iterations in SMEM
// =====================================================================
#define ITER_SMEM ((256 * 64 + 64 * 260 + 32 * 260 + 32 * 260 + 32 * 66) * 4)

// ts[r][m] = 0.5 * sum_d zs[r][d] * At[d][m]; thread: 4 rows x 2 m
__device__ __forceinline__ void tphase(const float* __restrict__ zs,
                                       const float* __restrict__ At,
                                       float* __restrict__ ts, int rg, int lane) {
    float acc[4][2];
    #pragma unroll
    for (int i = 0; i < 4; i++) { acc[i][0] = 0.f; acc[i][1] = 0.f; }
    #pragma unroll 2
    for (int d = 0; d < 256; d += 4) {
        float zk[4][4];
        #pragma unroll
        for (int i = 0; i < 4; i++) {
            float4 z4 = *(const float4*)(zs + (rg * 4 + i) * 260 + d);
            zk[i][0] = z4.x; zk[i][1] = z4.y; zk[i][2] = z4.z; zk[i][3] = z4.w;
        }
        #pragma unroll
        for (int k = 0; k < 4; k++) {
            float2 av = *(const float2*)(At + (d + k) * 64 + lane * 2);
            #pragma unroll
            for (int i = 0; i < 4; i++) {
                acc[i][0] = fmaf(zk[i][k], av.x, acc[i][0]);
                acc[i][1] = fmaf(zk[i][k], av.y, acc[i][1]);
            }
        }
    }
    #pragma unroll
    for (int i = 0; i < 4; i++) {
        float2 o; o.x = 0.5f * acc[i][0]; o.y = 0.5f * acc[i][1];
        *(float2*)(ts + (rg * 4 + i) * 66 + lane * 2) = o;
    }
}

// acc[i][j] = sum_m ts[r][m] * Mo[m][c]; thread: 4 rows x 8 cols
__device__ __forceinline__ void yphase(const float* __restrict__ ts,
                                       const float* __restrict__ Mo,
                                       int rg, int lane, float acc[4][8]) {
    #pragma unroll
    for (int i = 0; i < 4; i++)
        #pragma unroll
        for (int j = 0; j < 8; j++) acc[i][j] = 0.f;
    #pragma unroll 2
    for (int m = 0; m < 64; m++) {
        float4 m0 = *(const float4*)(Mo + m * 260 + lane * 8);
        float4 m1 = *(const float4*)(Mo + m * 260 + lane * 8 + 4);
        float mo[8] = {m0.x, m0.y, m0.z, m0.w, m1.x, m1.y, m1.z, m1.w};
        #pragma unroll
        for (int i = 0; i < 4; i++) {
            float tv = ts[(rg * 4 + i) * 66 + m];
            #pragma unroll
            for (int j = 0; j < 8; j++) acc[i][j] = fmaf(tv, mo[j], acc[i][j]);
        }
    }
}

__global__ __launch_bounds__(256, 1) void iter_kernel(
    const float* __restrict__ y0g, const float* __restrict__ bcong,
    const float* __restrict__ Ag, float* __restrict__ outg,
    const int* __restrict__ nip) {
    extern __shared__ float sm[];
    float* At = sm;             // [256][64]  A^T
    float* Mo = At + 256 * 64;  // [64][260]
    float* zs = Mo + 64 * 260;  // [32][260]
    float* rv = zs + 32 * 260;  // [32][260]
    float* ts = rv + 32 * 260;  // [32][66]
    const int tid = threadIdx.x;
    const int lane = tid & 31, rg = tid >> 5;
    const int row0 = blockIdx.x * 32;
    const int ni = *nip;

    for (int i = tid; i < 64 * 64; i += 256) {
        int m = i >> 6, d = (i & 63) << 2;
        float4 v = *(const float4*)(Ag + m * 256 + d);
        At[(d + 0) * 64 + m] = v.x; At[(d + 1) * 64 + m] = v.y;
        At[(d + 2) * 64 + m] = v.z; At[(d + 3) * 64 + m] = v.w;
    }
    for (int i = tid; i < 64 * 64; i += 256) {
        int m = i >> 6, c = (i & 63) << 2;
        *(float4*)(Mo + m * 260 + c) = *(const float4*)(g_Mop + m * 256 + c);
    }
    for (int i = tid; i < 32 * 64; i += 256) {
        int r = i >> 6, c = (i & 63) << 2;
        *(float4*)(zs + r * 260 + c) = *(const float4*)(y0g + (size_t)(row0 + r) * 256 + c);
    }
    __syncthreads();

    // rv = 0.5*y0 - (0.5*(y0 @ A^T) - bcon) @ Mop   (zs == y0 here)
    tphase(zs, At, ts, rg, lane);
    #pragma unroll
    for (int i = 0; i < 4; i++) {
        int r = rg * 4 + i;
        float2 bc = *(const float2*)(bcong + (size_t)(row0 + r) * 64 + lane * 2);
        ts[r * 66 + lane * 2]     -= bc.x;
        ts[r * 66 + lane * 2 + 1] -= bc.y;
    }
    __syncthreads();
    {
        float acc[4][8];
        yphase(ts, Mo, rg, lane, acc);
        #pragma unroll
        for (int i = 0; i < 4; i++) {
            int r = rg * 4 + i;
            #pragma unroll
            for (int j = 0; j < 8; j++) {
                int c = lane * 8 + j;
                rv[r * 260 + c] = 0.5f * zs[r * 260 + c] - acc[i][j];
            }
        }
    }
    __syncthreads();

    for (int it = 0; it < ni; it++) {
        tphase(zs, At, ts, rg, lane);
        __syncthreads();
        float acc[4][8];
        yphase(ts, Mo, rg, lane, acc);
        if (it == ni - 1) {
            #pragma unroll
            for (int i = 0; i < 4; i++) {
                int r = rg * 4 + i;
                #pragma unroll
                for (int j = 0; j < 8; j++) {
                    int c = lane * 8 + j;
                    float y = 0.5f * zs[r * 260 + c] - acc[i][j] + rv[r * 260 + c];
                    outg[(size_t)(row0 + r) * 256 + c] = y;
                }
            }
        } else {
            #pragma unroll
            for (int i = 0; i < 4; i++) {
                int r = rg * 4 + i;
                #pragma unroll
                for (int j = 0; j < 8; j++) {
                    int c = lane * 8 + j;
                    float z = zs[r * 260 + c];
                    float y = 0.5f * z - acc[i][j] + rv[r * 260 + c];
                    float w = fmaxf(2.f * y - z, 0.f);
                    zs[r * 260 + c] = z + OMEGA * (w - y);
                }
            }
        }
        __syncthreads();
    }
}

// =====================================================================
extern "C" void kernel_launch(void* const* d_in, const int* in_sizes, int n_in,
                              void* d_out, int out_size) {
    const float* x    = (const float*)d_in[0];
    const float* bcon = (const float*)d_in[1];
    const float* A    = (const float*)d_in[2];
    const float* W1   = (const float*)d_in[3];
    const float* b1   = (const float*)d_in[4];
    const float* W2   = (const float*)d_in[5];
    const float* b2   = (const float*)d_in[6];
    const float* W3   = (const float*)d_in[7];
    const float* b3   = (const float*)d_in[8];
    const float* Wout = (const float*)d_in[9];
    const float* bout = (const float*)d_in[10];
    const int*   nip  = (const int*)d_in[11];
    float* out = (float*)d_out;

    cudaFuncSetAttribute(setup_kernel, cudaFuncAttributeMaxDynamicSharedMemorySize, SETUP_SMEM);
    cudaFuncSetAttribute(iter_kernel,  cudaFuncAttributeMaxDynamicSharedMemorySize, ITER_SMEM);

    void *ph1, *ph2, *py0;
    cudaGetSymbolAddress(&ph1, g_h1);
    cudaGetSymbolAddress(&ph2, g_h2);
    cudaGetSymbolAddress(&py0, g_y0);
    float* h1 = (float*)ph1;
    float* h2 = (float*)ph2;
    float* y0 = (float*)py0;

    setup_kernel<<<1, 256, SETUP_SMEM>>>(A);
    gemm_bias<true ><<<dim3(8, 32), 256>>>(x,  W1, b1, h1, 4096, 512, 128);
    gemm_bias<true ><<<dim3(8, 32), 256>>>(h1, W2, b2, h2, 4096, 512, 512);
    gemm_bias<true ><<<dim3(8, 32), 256>>>(h2, W3, b3, h1, 4096, 512, 512);
    gemm_bias<false><<<dim3(4, 32), 256>>>(h1, Wout, bout, y0, 4096, 256, 512);
    iter_kernel<<<128, 256, ITER_SMEM>>>(y0, bcon, A, out, nip);
}

// round 4
// speedup vs baseline: 1.2746x; 1.2746x over previous
#include <cuda_runtime.h>

#define OMEGA 1.7f

// packed fp32x2 FMA: d = a*b + d (elementwise on two packed floats)
#define FFMA2(d, a, b) asm("fma.rn.f32x2 %0, %1, %2, %0;" : "+l"(d) : "l"(a), "l"(b))

// -------- global scratch (allocations are forbidden) --------
__device__ float g_Mop[64 * 256];
__device__ float g_h1[4096 * 512];
__device__ float g_h2[4096 * 512];
__device__ float g_y0[4096 * 256];

// =====================================================================
// setup: G = A A^T (64x64), K = inv(G) via Gauss-Jordan, Mop = K @ A
// =====================================================================
#define SETUP_SMEM ((64 * 260 + 64 * 130) * 4)

__global__ void setup_kernel(const float* __restrict__ A) {
    extern __shared__ float sm[];
    float* As = sm;              // [64][260] staged A
    float* G  = sm + 64 * 260;   // [64][130] augmented [G | I]
    __shared__ float colp[64];
    const int tid = threadIdx.x;

    for (int i = tid; i < 64 * 64; i += 256) {
        int m = i >> 6, d = (i & 63) << 2;
        *(float4*)(As + m * 260 + d) = *(const float4*)(A + m * 256 + d);
    }
    __syncthreads();

    for (int o = tid; o < 64 * 64; o += 256) {
        int i = o >> 6, j = o & 63;
        const float4* ai = (const float4*)(As + i * 260);
        const float4* aj = (const float4*)(As + j * 260);
        float s = 0.f;
        #pragma unroll 8
        for (int d4 = 0; d4 < 64; d4++) {
            float4 a = ai[d4], b = aj[d4];
            s += a.x * b.x + a.y * b.y + a.z * b.z + a.w * b.w;
        }
        G[i * 130 + j] = s;
        G[i * 130 + 64 + j] = (i == j) ? 1.f : 0.f;
    }
    __syncthreads();

    for (int p = 0; p < 64; p++) {
        float pinv = 1.f / G[p * 130 + p];
        if (tid < 64) colp[tid] = G[tid * 130 + p];
        __syncthreads();
        if (tid < 128) G[p * 130 + tid] *= pinv;
        __syncthreads();
        for (int e = tid; e < 64 * 128; e += 256) {
            int i = e >> 7, c = e & 127;
            if (i != p) G[i * 130 + c] -= colp[i] * G[p * 130 + c];
        }
        __syncthreads();
    }

    for (int o = tid; o < 64 * 256; o += 256) {
        int m = o >> 8, d = o & 255;
        float s = 0.f;
        #pragma unroll 8
        for (int j = 0; j < 64; j++) s += G[m * 130 + 64 + j] * As[j * 260 + d];
        g_Mop[o] = s;
    }
}

// =====================================================================
// trunk GEMM: C = act(Amat @ Bmat + bias), BM=128 BN=64 BK=16, 256 thr
// =====================================================================
template <bool RELU>
__global__ void gemm_bias(const float* __restrict__ Am, const float* __restrict__ Bm,
                          const float* __restrict__ bias, float* __restrict__ C,
                          int M, int N, int K) {
    __shared__ float As[16][132];
    __shared__ float Bs[16][68];
    const int tid = threadIdx.x;
    const int bm = blockIdx.y * 128, bn = blockIdx.x * 64;
    const int tx = tid & 15, ty = tid >> 4;

    float acc[8][4];
    #pragma unroll
    for (int i = 0; i < 8; i++)
        #pragma unroll
        for (int j = 0; j < 4; j++) acc[i][j] = 0.f;

    const int ar = tid >> 2, akc = (tid & 3) << 2;
    const int bkr = tid >> 4, bnc = (tid & 15) << 2;

    for (int k0 = 0; k0 < K; k0 += 16) {
        #pragma unroll
        for (int rr = 0; rr < 2; rr++) {
            int r = ar + rr * 64;
            float4 v = *(const float4*)(Am + (size_t)(bm + r) * K + k0 + akc);
            As[akc + 0][r] = v.x; As[akc + 1][r] = v.y;
            As[akc + 2][r] = v.z; As[akc + 3][r] = v.w;
        }
        *(float4*)(&Bs[bkr][bnc]) = *(const float4*)(Bm + (size_t)(k0 + bkr) * N + bn + bnc);
        __syncthreads();

        #pragma unroll
        for (int kk = 0; kk < 16; kk++) {
            float a[8], b[4];
            #pragma unroll
            for (int i = 0; i < 8; i++) a[i] = As[kk][ty * 8 + i];
            #pragma unroll
            for (int j = 0; j < 4; j++) b[j] = Bs[kk][tx * 4 + j];
            #pragma unroll
            for (int i = 0; i < 8; i++)
                #pragma unroll
                for (int j = 0; j < 4; j++) acc[i][j] = fmaf(a[i], b[j], acc[i][j]);
        }
        __syncthreads();
    }

    float4 bv = *(const float4*)(bias + bn + tx * 4);
    #pragma unroll
    for (int i = 0; i < 8; i++) {
        float4 o;
        o.x = acc[i][0] + bv.x; o.y = acc[i][1] + bv.y;
        o.z = acc[i][2] + bv.z; o.w = acc[i][3] + bv.w;
        if (RELU) {
            o.x = fmaxf(o.x, 0.f); o.y = fmaxf(o.y, 0.f);
            o.z = fmaxf(o.z, 0.f); o.w = fmaxf(o.w, 0.f);
        }
        *(float4*)(C + (size_t)(bm + ty * 8 + i) * N + bn + tx * 4) = o;
    }
}

// =====================================================================
// iteration kernel: persistent 32-row tile, f32x2-packed, warp-private
//   SMEM: As [64][258]  row-major A          (66.0 KB)
//         MoT[256][66]  Mop transposed       (67.6 KB)
//         zs [32][260]  z state              (33.3 KB)
//         rv [32][260]  affine constant      (33.3 KB)
//         ts [32][66]   t = 0.5*z@A^T        ( 8.4 KB)
// =====================================================================
#define ITER_SMEM ((64 * 258 + 256 * 66 + 32 * 260 + 32 * 260 + 32 * 66) * 4)

typedef unsigned long long ull;

// ts[r][m] = 0.5 * sum_d zs[r][d] * A[m][d]; packed over d; warp-private rows.
__device__ __forceinline__ void tphase(const float* __restrict__ zs,
                                       const float* __restrict__ Asm,
                                       float* __restrict__ ts, int rg, int lane) {
    ull acc[4][2];
    #pragma unroll
    for (int i = 0; i < 4; i++) { acc[i][0] = 0ull; acc[i][1] = 0ull; }
    const float* zp0 = zs + rg * 4 * 260;
    const float* a0 = Asm + lane * 258;
    const float* a1 = Asm + (lane + 32) * 258;
    #pragma unroll 4
    for (int d = 0; d < 256; d += 2) {
        ull ap0 = *(const ull*)(a0 + d);
        ull ap1 = *(const ull*)(a1 + d);
        #pragma unroll
        for (int i = 0; i < 4; i++) {
            ull zp = *(const ull*)(zp0 + i * 260 + d);
            FFMA2(acc[i][0], zp, ap0);
            FFMA2(acc[i][1], zp, ap1);
        }
    }
    #pragma unroll
    for (int i = 0; i < 4; i++) {
        float2 f0 = *(float2*)&acc[i][0];
        float2 f1 = *(float2*)&acc[i][1];
        ts[(rg * 4 + i) * 66 + lane]      = 0.5f * (f0.x + f0.y);
        ts[(rg * 4 + i) * 66 + lane + 32] = 0.5f * (f1.x + f1.y);
    }
}

// s[i][j] = sum_m ts[r][m] * Mop[m][c], c = lane + 32*j; packed over m.
__device__ __forceinline__ void yphase(const float* __restrict__ ts,
                                       const float* __restrict__ MoT,
                                       int rg, int lane, float s[4][8]) {
    ull acc[4][8];
    #pragma unroll
    for (int i = 0; i < 4; i++)
        #pragma unroll
        for (int j = 0; j < 8; j++) acc[i][j] = 0ull;
    const float* tp = ts + rg * 4 * 66;
    const float* mp = MoT + lane * 66;
    #pragma unroll 2
    for (int m = 0; m < 64; m += 2) {
        ull a[4], b[8];
        #pragma unroll
        for (int i = 0; i < 4; i++) a[i] = *(const ull*)(tp + i * 66 + m);
        #pragma unroll
        for (int j = 0; j < 8; j++) b[j] = *(const ull*)(mp + j * 32 * 66 + m);
        #pragma unroll
        for (int i = 0; i < 4; i++)
            #pragma unroll
            for (int j = 0; j < 8; j++) FFMA2(acc[i][j], a[i], b[j]);
    }
    #pragma unroll
    for (int i = 0; i < 4; i++)
        #pragma unroll
        for (int j = 0; j < 8; j++) {
            float2 f = *(float2*)&acc[i][j];
            s[i][j] = f.x + f.y;
        }
}

__global__ __launch_bounds__(256, 1) void iter_kernel(
    const float* __restrict__ y0g, const float* __restrict__ bcong,
    const float* __restrict__ Ag, float* __restrict__ outg,
    const int* __restrict__ nip) {
    extern __shared__ float sm[];
    float* Asm = sm;               // [64][258]
    float* MoT = Asm + 64 * 258;   // [256][66]
    float* zs  = MoT + 256 * 66;   // [32][260]
    float* rv  = zs + 32 * 260;    // [32][260]
    float* ts  = rv + 32 * 260;    // [32][66]
    const int tid = threadIdx.x;
    const int lane = tid & 31, rg = tid >> 5;
    const int row0 = blockIdx.x * 32;
    const int ni = *nip;

    // stage A row-major (stride 258), float2 loads
    for (int i = tid; i < 64 * 128; i += 256) {
        int m = i >> 7, d = (i & 127) << 1;
        *(float2*)(Asm + m * 258 + d) = *(const float2*)(Ag + m * 256 + d);
    }
    // stage Mop transposed
    for (int i = tid; i < 64 * 256; i += 256) {
        int m = i >> 8, c = i & 255;
        MoT[c * 66 + m] = g_Mop[i];
    }
    // stage z = y0
    for (int i = tid; i < 32 * 64; i += 256) {
        int r = i >> 6, c = (i & 63) << 2;
        *(float4*)(zs + r * 260 + c) = *(const float4*)(y0g + (size_t)(row0 + r) * 256 + c);
    }
    __syncthreads();

    // rv = 0.5*y0 - (0.5*(y0 @ A^T) - bcon) @ Mop     (zs == y0 here)
    tphase(zs, Asm, ts, rg, lane);
    #pragma unroll
    for (int i = 0; i < 4; i++) {
        int r = rg * 4 + i;
        ts[r * 66 + lane]      -= bcong[(size_t)(row0 + r) * 64 + lane];
        ts[r * 66 + lane + 32] -= bcong[(size_t)(row0 + r) * 64 + lane + 32];
    }
    __syncwarp();
    {
        float s[4][8];
        yphase(ts, MoT, rg, lane, s);
        #pragma unroll
        for (int i = 0; i < 4; i++) {
            int r = rg * 4 + i;
            #pragma unroll
            for (int j = 0; j < 8; j++) {
                int c = lane + 32 * j;
                rv[r * 260 + c] = 0.5f * zs[r * 260 + c] - s[i][j];
            }
        }
    }
    __syncwarp();

    for (int it = 0; it < ni; it++) {
        tphase(zs, Asm, ts, rg, lane);
        __syncwarp();
        float s[4][8];
        yphase(ts, MoT, rg, lane, s);
        if (it == ni - 1) {
            #pragma unroll
            for (int i = 0; i < 4; i++) {
                int r = rg * 4 + i;
                #pragma unroll
                for (int j = 0; j < 8; j++) {
                    int c = lane + 32 * j;
                    float y = 0.5f * zs[r * 260 + c] - s[i][j] + rv[r * 260 + c];
                    outg[(size_t)(row0 + r) * 256 + c] = y;
                }
            }
        } else {
            #pragma unroll
            for (int i = 0; i < 4; i++) {
                int r = rg * 4 + i;
                #pragma unroll
                for (int j = 0; j < 8; j++) {
                    int c = lane + 32 * j;
                    float z = zs[r * 260 + c];
                    float y = 0.5f * z - s[i][j] + rv[r * 260 + c];
                    float w = fmaxf(2.f * y - z, 0.f);
                    zs[r * 260 + c] = z + OMEGA * (w - y);
                }
            }
            __syncwarp();
        }
    }
}

// =====================================================================
extern "C" void kernel_launch(void* const* d_in, const int* in_sizes, int n_in,
                              void* d_out, int out_size) {
    const float* x    = (const float*)d_in[0];
    const float* bcon = (const float*)d_in[1];
    const float* A    = (const float*)d_in[2];
    const float* W1   = (const float*)d_in[3];
    const float* b1   = (const float*)d_in[4];
    const float* W2   = (const float*)d_in[5];
    const float* b2   = (const float*)d_in[6];
    const float* W3   = (const float*)d_in[7];
    const float* b3   = (const float*)d_in[8];
    const float* Wout = (const float*)d_in[9];
    const float* bout = (const float*)d_in[10];
    const int*   nip  = (const int*)d_in[11];
    float* out = (float*)d_out;

    cudaFuncSetAttribute(setup_kernel, cudaFuncAttributeMaxDynamicSharedMemorySize, SETUP_SMEM);
    cudaFuncSetAttribute(iter_kernel,  cudaFuncAttributeMaxDynamicSharedMemorySize, ITER_SMEM);

    void *ph1, *ph2, *py0;
    cudaGetSymbolAddress(&ph1, g_h1);
    cudaGetSymbolAddress(&ph2, g_h2);
    cudaGetSymbolAddress(&py0, g_y0);
    float* h1 = (float*)ph1;
    float* h2 = (float*)ph2;
    float* y0 = (float*)py0;

    setup_kernel<<<1, 256, SETUP_SMEM>>>(A);
    gemm_bias<true ><<<dim3(8, 32), 256>>>(x,  W1, b1, h1, 4096, 512, 128);
    gemm_bias<true ><<<dim3(8, 32), 256>>>(h1, W2, b2, h2, 4096, 512, 512);
    gemm_bias<true ><<<dim3(8, 32), 256>>>(h2, W3, b3, h1, 4096, 512, 512);
    gemm_bias<false><<<dim3(4, 32), 256>>>(h1, Wout, bout, y0, 4096, 256, 512);
    iter_kernel<<<128, 256, ITER_SMEM>>>(y0, bcon, A, out, nip);
}